// round 5
// baseline (speedup 1.0000x reference)
#include <cuda_runtime.h>
#include <cstdint>
#include <cstddef>

#define NN 4096   // nodes
#define DD 128    // embedding dim
#define RR 8      // relations
#define OO 128    // output dim
#define NB 4096   // batch

#define BM 128
#define BK 32
#define PAD_A 36
#define PAD_B 136

// scratch (device globals: no allocations allowed)
__device__ float g_W[(size_t)RR * NN * OO];     // W[r] = emb @ rk[r]        (16 MB)
__device__ float g_part[(size_t)RR * NN * OO];  // partial: adj[r] @ W[r]    (16 MB)

__device__ __forceinline__ float rna_tf32(float x) {
    uint32_t u;
    asm("cvt.rna.tf32.f32 %0, %1;" : "=r"(u) : "f"(x));
    return __uint_as_float(u);
}

// tf32 tensor-core GEMM with split-precision B operand:
//   C[r] = A[r] (128*gridX x K) @ B[r] (K x 128)
// A is rounded to tf32 (rna, unbiased). B is decomposed B = B_hi + B_lo
// (two tf32 values, ~21 mantissa bits) and consumed with 2 MMAs -> B is
// effectively exact; only A contributes ~2.8e-4 unbiased noise.
// grid = (M/128, R). Each CTA owns a disjoint 128x128 output tile.
__global__ __launch_bounds__(256, 2)
void gemm_tf32_split_kernel(const float* __restrict__ A0, size_t strideAr, size_t lda,
                            const float* __restrict__ B0, size_t strideBr,
                            float* __restrict__ C0, size_t strideCr,
                            int K) {
    extern __shared__ float smem[];
    float* As = smem;                      // BM * PAD_A
    float* Bh = As + BM * PAD_A;           // BK * PAD_B
    float* Bl = Bh + BK * PAD_B;           // BK * PAD_B

    const int mtile = blockIdx.x;
    const int r = blockIdx.y;
    const float* Ag = A0 + (size_t)r * strideAr + (size_t)mtile * BM * lda;
    const float* Bg = B0 + (size_t)r * strideBr;
    float* Cg = C0 + (size_t)r * strideCr + (size_t)mtile * BM * OO;

    const int tid  = threadIdx.x;
    const int lane = tid & 31;
    const int warp = tid >> 5;
    const int wm   = warp >> 2;   // 0..1  (M direction, 64 rows each)
    const int wn   = warp & 3;    // 0..3  (N direction, 32 cols each)
    const int grp  = lane >> 2;   // 0..7
    const int tig  = lane & 3;    // 0..3

    float acc[4][4][4];
#pragma unroll
    for (int i = 0; i < 4; i++)
#pragma unroll
        for (int j = 0; j < 4; j++) {
            acc[i][j][0] = 0.f; acc[i][j][1] = 0.f;
            acc[i][j][2] = 0.f; acc[i][j][3] = 0.f;
        }

    float4 ra[4], rb[4];

    // prologue: stage k-tile 0
#pragma unroll
    for (int j = 0; j < 4; j++) {
        int fi = tid + j * 256;   // 0..1023
        ra[j] = *reinterpret_cast<const float4*>(Ag + (size_t)(fi >> 3) * lda + ((fi & 7) << 2));
        rb[j] = *reinterpret_cast<const float4*>(Bg + (size_t)(fi >> 5) * OO + ((fi & 31) << 2));
    }

    const int KT = K / BK;
#pragma unroll 1
    for (int kt = 0; kt < KT; ++kt) {
        __syncthreads();
#pragma unroll
        for (int j = 0; j < 4; j++) {
            int fi = tid + j * 256;
            // A: round to tf32 (unbiased) at staging time
            float4 va = ra[j];
            va.x = rna_tf32(va.x); va.y = rna_tf32(va.y);
            va.z = rna_tf32(va.z); va.w = rna_tf32(va.w);
            *reinterpret_cast<float4*>(As + (fi >> 3) * PAD_A + ((fi & 7) << 2)) = va;
            // B: hi/lo split (b = hi + lo, both exactly representable in tf32)
            float4 vb = rb[j];
            float4 vh, vl;
            vh.x = rna_tf32(vb.x); vl.x = rna_tf32(vb.x - vh.x);
            vh.y = rna_tf32(vb.y); vl.y = rna_tf32(vb.y - vh.y);
            vh.z = rna_tf32(vb.z); vl.z = rna_tf32(vb.z - vh.z);
            vh.w = rna_tf32(vb.w); vl.w = rna_tf32(vb.w - vh.w);
            int boff = (fi >> 5) * PAD_B + ((fi & 31) << 2);
            *reinterpret_cast<float4*>(Bh + boff) = vh;
            *reinterpret_cast<float4*>(Bl + boff) = vl;
        }
        __syncthreads();
        if (kt + 1 < KT) {   // prefetch next k-tile while computing this one
            const float* Ak = Ag + (size_t)(kt + 1) * BK;
            const float* Bk = Bg + (size_t)(kt + 1) * BK * OO;
#pragma unroll
            for (int j = 0; j < 4; j++) {
                int fi = tid + j * 256;
                ra[j] = *reinterpret_cast<const float4*>(Ak + (size_t)(fi >> 3) * lda + ((fi & 7) << 2));
                rb[j] = *reinterpret_cast<const float4*>(Bk + (size_t)(fi >> 5) * OO + ((fi & 31) << 2));
            }
        }
#pragma unroll
        for (int ks = 0; ks < BK; ks += 8) {
            uint32_t af[4][4], bfh[4][2], bfl[4][2];
#pragma unroll
            for (int mi = 0; mi < 4; mi++) {
                const float* p = As + (wm * 64 + mi * 16 + grp) * PAD_A + ks + tig;
                af[mi][0] = __float_as_uint(p[0]);
                af[mi][1] = __float_as_uint(p[8 * PAD_A]);
                af[mi][2] = __float_as_uint(p[4]);
                af[mi][3] = __float_as_uint(p[8 * PAD_A + 4]);
            }
#pragma unroll
            for (int ni = 0; ni < 4; ni++) {
                int boff = (ks + tig) * PAD_B + wn * 32 + ni * 8 + grp;
                bfh[ni][0] = __float_as_uint(Bh[boff]);
                bfh[ni][1] = __float_as_uint(Bh[boff + 4 * PAD_B]);
                bfl[ni][0] = __float_as_uint(Bl[boff]);
                bfl[ni][1] = __float_as_uint(Bl[boff + 4 * PAD_B]);
            }
#pragma unroll
            for (int mi = 0; mi < 4; mi++)
#pragma unroll
                for (int ni = 0; ni < 4; ni++) {
                    asm volatile(
                        "mma.sync.aligned.m16n8k8.row.col.f32.tf32.tf32.f32 "
                        "{%0,%1,%2,%3}, {%4,%5,%6,%7}, {%8,%9}, {%0,%1,%2,%3};\n"
                        : "+f"(acc[mi][ni][0]), "+f"(acc[mi][ni][1]),
                          "+f"(acc[mi][ni][2]), "+f"(acc[mi][ni][3])
                        : "r"(af[mi][0]), "r"(af[mi][1]), "r"(af[mi][2]), "r"(af[mi][3]),
                          "r"(bfh[ni][0]), "r"(bfh[ni][1]));
                    asm volatile(
                        "mma.sync.aligned.m16n8k8.row.col.f32.tf32.tf32.f32 "
                        "{%0,%1,%2,%3}, {%4,%5,%6,%7}, {%8,%9}, {%0,%1,%2,%3};\n"
                        : "+f"(acc[mi][ni][0]), "+f"(acc[mi][ni][1]),
                          "+f"(acc[mi][ni][2]), "+f"(acc[mi][ni][3])
                        : "r"(af[mi][0]), "r"(af[mi][1]), "r"(af[mi][2]), "r"(af[mi][3]),
                          "r"(bfl[ni][0]), "r"(bfl[ni][1]));
                }
        }
    }

    // epilogue: disjoint tile store
#pragma unroll
    for (int mi = 0; mi < 4; mi++) {
        int row0 = wm * 64 + mi * 16 + grp;
#pragma unroll
        for (int ni = 0; ni < 4; ni++) {
            int col = wn * 32 + ni * 8 + tig * 2;
            *reinterpret_cast<float2*>(Cg + (size_t)row0 * OO + col) =
                make_float2(acc[mi][ni][0], acc[mi][ni][1]);
            *reinterpret_cast<float2*>(Cg + (size_t)(row0 + 8) * OO + col) =
                make_float2(acc[mi][ni][2], acc[mi][ni][3]);
        }
    }
}

// out[b] = e[b] @ self_kernel + sum_r g_part[r][idx[b]]   (pure fp32, exact)
__global__ void finalize_kernel(const float* __restrict__ he, const int* __restrict__ hidx,
                                const float* __restrict__ te, const int* __restrict__ tidx,
                                const float* __restrict__ sk, float* __restrict__ out) {
    const int b = blockIdx.x;           // 0..8191 (head: 0..4095, tail: 4096..8191)
    const int o = threadIdx.x;          // 0..127
    const bool is_tail = b >= NB;
    const int bb = is_tail ? b - NB : b;
    const float* e = (is_tail ? te : he) + (size_t)bb * DD;
    const int idx = (is_tail ? tidx : hidx)[bb];

    __shared__ float es[DD];
    es[o] = e[o];
    __syncthreads();

    float acc = 0.f;
#pragma unroll
    for (int rr = 0; rr < RR; rr++)
        acc += g_part[((size_t)rr * NN + idx) * OO + o];
#pragma unroll 16
    for (int d = 0; d < DD; ++d)
        acc = fmaf(es[d], sk[d * OO + o], acc);

    out[(size_t)b * OO + o] = acc;
}

extern "C" void kernel_launch(void* const* d_in, const int* in_sizes, int n_in,
                              void* d_out, int out_size) {
    const float* emb  = (const float*)d_in[0];
    const int*   hidx = (const int*)  d_in[1];
    const float* he   = (const float*)d_in[2];
    const int*   tidx = (const int*)  d_in[3];
    const float* te   = (const float*)d_in[4];
    const float* adj  = (const float*)d_in[5];
    const float* rk   = (const float*)d_in[6];
    const float* sk   = (const float*)d_in[7];
    float* out = (float*)d_out;

    float *Wp = nullptr, *Pp = nullptr;
    cudaGetSymbolAddress((void**)&Wp, g_W);
    cudaGetSymbolAddress((void**)&Pp, g_part);

    const size_t smem_bytes = (size_t)(BM * PAD_A + 2 * BK * PAD_B) * sizeof(float);
    static bool attr_set = false;
    if (!attr_set) {
        cudaFuncSetAttribute(gemm_tf32_split_kernel,
                             cudaFuncAttributeMaxDynamicSharedMemorySize,
                             (int)smem_bytes);
        attr_set = true;
    }

    // Pass 1: W[r] = emb @ rk[r]      (M=4096, K=128, shared A across r)
    // B (=rk) split -> rk exact; emb rna noise ~2.8e-4
    gemm_tf32_split_kernel<<<dim3(NN / BM, RR), 256, smem_bytes>>>(
        emb, 0, (size_t)DD,
        rk, (size_t)DD * OO,
        Wp, (size_t)NN * OO,
        DD);

    // Pass 2: g_part[r] = adj[r] @ W[r]   (M=4096, K=4096) — streams 512 MB once
    // B (=W) split -> W exact; adj rna noise ~2.8e-4
    gemm_tf32_split_kernel<<<dim3(NN / BM, RR), 256, smem_bytes>>>(
        adj, (size_t)NN * NN, (size_t)NN,
        Wp, (size_t)NN * OO,
        Pp, (size_t)NN * OO,
        NN);

    // Pass 3: gather + self-kernel GEMM, both branches
    finalize_kernel<<<2 * NB, DD>>>(he, hidx, te, tidx, sk, out);
}